// round 16
// baseline (speedup 1.0000x reference)
#include <cuda_runtime.h>
#include <cstdint>

// ============================================================================
// FarthestSubsample: B=16, Cc=3, Cv=64, N=8192, npoint=4096
//
// R16: single-CTA barrier-free FPS + replicated fused gather (ONE kernel).
//   - 8 replica CTAs per batch (128 CTAs); each runs the identical
//     deterministic FPS (1024 thr, 8 pts/thread, f32x2 packed math),
//     keeps selected indices in its own SMEM, then writes 1/8 of the output.
//   - Per-step exchange, all intra-CTA and barrier-free: warp redux ->
//     lane0 posts tagged 8B key to slot[parity*32+warp] -> every lane
//     volatile-polls slot[parity*32+lane] until tag matches -> bfly5.
//     Parity double-buffer safe by induction (writer of step t+2 passed
//     step t+1, which required all warps to have consumed step t).
//
// Bit-exact invariants (validated R7-R15):
//   init: k2=threefry(key(42),(0,1)); farthest0[b]=((o0^o1)(k2,(0,b)))&8191
//   dist: d = fma(dz,dz, fma(dx,dx, dy*dy)); argmax first-occurrence.
// Output: [new_coords (16,3,4096)] ++ [new_values (16,64,4096)]
// ============================================================================

#define BATCH    16
#define NPTS     8192
#define NPOINT   4096
#define REP      8                     // replica CTAs per batch
#define THREADS  1024
#define NWARPS   (THREADS / 32)        // 32
#define PPT      (NPTS / THREADS)      // 8
#define NPAIR    (PPT / 2)             // 4
#define SLICE    (NPOINT / REP)        // 512
#define NCHAN    67                    // 3 coords + 64 values

static inline uint32_t rotl32(uint32_t x, uint32_t r) { return (x << r) | (x >> (32 - r)); }

static void tf2x32_block(uint32_t k0, uint32_t k1, uint32_t x0, uint32_t x1,
                         uint32_t* o0, uint32_t* o1) {
    const uint32_t rA[4] = {13, 15, 26, 6};
    const uint32_t rB[4] = {17, 29, 16, 24};
    uint32_t ks0 = k0, ks1 = k1, ks2 = k0 ^ k1 ^ 0x1BD11BDAu;
    x0 += ks0; x1 += ks1;
    for (int i = 0; i < 4; i++) { x0 += x1; x1 = rotl32(x1, rA[i]); x1 ^= x0; }
    x0 += ks1; x1 += ks2 + 1u;
    for (int i = 0; i < 4; i++) { x0 += x1; x1 = rotl32(x1, rB[i]); x1 ^= x0; }
    x0 += ks2; x1 += ks0 + 2u;
    for (int i = 0; i < 4; i++) { x0 += x1; x1 = rotl32(x1, rA[i]); x1 ^= x0; }
    x0 += ks0; x1 += ks1 + 3u;
    for (int i = 0; i < 4; i++) { x0 += x1; x1 = rotl32(x1, rB[i]); x1 ^= x0; }
    x0 += ks1; x1 += ks2 + 4u;
    for (int i = 0; i < 4; i++) { x0 += x1; x1 = rotl32(x1, rA[i]); x1 ^= x0; }
    x0 += ks2; x1 += ks0 + 5u;
    *o0 = x0; *o1 = x1;
}

struct Cfg { int v[BATCH]; };

static void build_config(Cfg* cfg) {
    uint32_t k2a, k2b;
    tf2x32_block(0u, 42u, 0u, 1u, &k2a, &k2b);
    for (int b = 0; b < BATCH; b++) {
        uint32_t o0, o1;
        tf2x32_block(k2a, k2b, 0u, (uint32_t)b, &o0, &o1);
        cfg->v[b] = (int)((o0 ^ o1) & (NPTS - 1));
    }
}

// ---- helpers ----
__device__ __forceinline__ uint32_t smem_u32(const void* p) {
    uint32_t a;
    asm("{ .reg .u64 t; cvta.to.shared.u64 t, %1; cvt.u32.u64 %0, t; }"
        : "=r"(a) : "l"(p));
    return a;
}
__device__ __forceinline__ void st_vol_u64(uint32_t addr, unsigned long long v) {
    asm volatile("st.volatile.shared.u64 [%0], %1;" :: "r"(addr), "l"(v) : "memory");
}
__device__ __forceinline__ unsigned long long ld_vol_u64(uint32_t addr) {
    unsigned long long v;
    asm volatile("ld.volatile.shared.u64 %0, [%1];" : "=l"(v) : "r"(addr) : "memory");
    return v;
}
__device__ __forceinline__ unsigned long long pack2(float lo, float hi) {
    unsigned long long r;
    asm("mov.b64 %0, {%1, %2};" : "=l"(r) : "f"(lo), "f"(hi));
    return r;
}
__device__ __forceinline__ void unpack2(unsigned long long v, float& lo, float& hi) {
    asm("mov.b64 {%0, %1}, %2;" : "=f"(lo), "=f"(hi) : "l"(v));
}
__device__ __forceinline__ unsigned long long add2(unsigned long long a, unsigned long long b) {
    unsigned long long r; asm("add.rn.f32x2 %0, %1, %2;" : "=l"(r) : "l"(a), "l"(b)); return r;
}
__device__ __forceinline__ unsigned long long mul2(unsigned long long a, unsigned long long b) {
    unsigned long long r; asm("mul.rn.f32x2 %0, %1, %2;" : "=l"(r) : "l"(a), "l"(b)); return r;
}
__device__ __forceinline__ unsigned long long fma2(unsigned long long a, unsigned long long b,
                                                   unsigned long long c) {
    unsigned long long r; asm("fma.rn.f32x2 %0, %1, %2, %3;" : "=l"(r) : "l"(a), "l"(b), "l"(c)); return r;
}

#define CO (BATCH * 3 * NPOINT)

__global__ __launch_bounds__(THREADS, 1)
void fps_kernel(const float* __restrict__ coords,
                const float* __restrict__ values,
                float* __restrict__ out, Cfg cfg) {
    extern __shared__ float smem[];
    float* sx = smem;                            // NPTS
    float* sy = smem + NPTS;                     // NPTS
    float* sz = smem + 2 * NPTS;                 // NPTS
    int*   sidx = (int*)(smem + 3 * NPTS);       // NPOINT
    unsigned long long* slots =
        (unsigned long long*)(smem + 3 * NPTS + NPOINT);  // 2*NWARPS

    const int b   = blockIdx.x / REP;
    const int rep = blockIdx.x % REP;
    const int tid  = threadIdx.x;
    const int lane = tid & 31;
    const int warp = tid >> 5;
    const float* cb = coords + (size_t)b * 3 * NPTS;
    const float* vb = values + (size_t)b * 64 * NPTS;

    for (int i = tid; i < NPTS; i += THREADS) {
        sx[i] = cb[i]; sy[i] = cb[NPTS + i]; sz[i] = cb[2 * NPTS + i];
    }
    unsigned long long p2x[NPAIR], p2y[NPAIR], p2z[NPAIR];
    float dist[PPT];
#pragma unroll
    for (int k = 0; k < NPAIR; k++) {
        int g0 = tid + (2 * k) * THREADS;
        int g1 = tid + (2 * k + 1) * THREADS;
        p2x[k] = pack2(cb[g0], cb[g1]);
        p2y[k] = pack2(cb[NPTS + g0], cb[NPTS + g1]);
        p2z[k] = pack2(cb[2 * NPTS + g0], cb[2 * NPTS + g1]);
        dist[2 * k] = 1e10f; dist[2 * k + 1] = 1e10f;
    }
    if (tid < 2 * NWARPS) slots[tid] = 0ull;     // tag 0 never expected
    __syncthreads();

    const uint32_t slots_a = smem_u32(slots);
    int farthest = cfg.v[b];

    for (int t = 0; t < NPOINT; t++) {
        if (tid == 0) sidx[t] = farthest;

        const float cx = sx[farthest], cy = sy[farthest], cz = sz[farthest];
        const unsigned long long ncx = pack2(-cx, -cx);
        const unsigned long long ncy = pack2(-cy, -cy);
        const unsigned long long ncz = pack2(-cz, -cz);

        float bv = -1.0f; int bi = 0;
#pragma unroll
        for (int k = 0; k < NPAIR; k++) {
            unsigned long long dx = add2(p2x[k], ncx);
            unsigned long long dy = add2(p2y[k], ncy);
            unsigned long long dz = add2(p2z[k], ncz);
            // bit-exact V2: d = fma(dz,dz, fma(dx,dx, dy*dy)) per lane
            unsigned long long d2 = fma2(dz, dz, fma2(dx, dx, mul2(dy, dy)));
            float dlo, dhi; unpack2(d2, dlo, dhi);
            float n0 = fminf(dist[2 * k], dlo);
            float n1 = fminf(dist[2 * k + 1], dhi);
            dist[2 * k] = n0; dist[2 * k + 1] = n1;
            if (n0 > bv) { bv = n0; bi = tid + (2 * k) * THREADS; }
            if (n1 > bv) { bv = n1; bi = tid + (2 * k + 1) * THREADS; }
        }

        // warp argmax via redux (dist >= 0 -> float bits monotone)
        uint32_t fb   = __float_as_uint(bv);
        uint32_t wmax = __reduce_max_sync(0xffffffffu, fb);
        uint32_t cand = (fb == wmax) ? (uint32_t)bi : 0xffffffffu;
        uint32_t widx = __reduce_min_sync(0xffffffffu, cand);
        const uint32_t tag = (uint32_t)((t + 1) & 0x1fff);
        // key = {fbits:[26,58) | invidx:[13,26) | tag:[0,13)}
        unsigned long long key = ((unsigned long long)wmax << 26)
                               | ((unsigned long long)(NPTS - 1 - widx) << 13)
                               | (unsigned long long)tag;

        const uint32_t par = (uint32_t)(t & 1) * NWARPS;
        if (lane == 0)
            st_vol_u64(slots_a + (par + (uint32_t)warp) * 8, key);

        // every lane polls one of the 32 slots of this parity
        {
            uint32_t a = slots_a + (par + (uint32_t)lane) * 8;
            unsigned long long v;
            do { v = ld_vol_u64(a); } while ((uint32_t)(v & 0x1fff) != tag);
            key = v;
        }
#pragma unroll
        for (int off = 16; off > 0; off >>= 1) {
            unsigned long long o = __shfl_xor_sync(0xffffffffu, key, off);
            if (o > key) key = o;
        }
        farthest = (int)(NPTS - 1) - (int)((key >> 13) & 0x1fff);
    }

    // ---- fused gather: this replica writes output slice [rep*512, rep*512+512) ----
    __syncthreads();
    const int i0 = rep * SLICE;
    for (int k = tid; k < NCHAN * SLICE; k += THREADS) {
        int c  = k / SLICE;          // channel 0..66
        int io = k - c * SLICE;
        int i  = i0 + io;
        int n  = sidx[i];
        float v;
        size_t e;
        if (c < 3) {
            v = cb[(size_t)c * NPTS + n];
            e = ((size_t)(b * 3 + c)) * NPOINT + (size_t)i;
        } else {
            v = vb[(size_t)(c - 3) * NPTS + n];
            e = (size_t)CO + ((size_t)(b * 64 + (c - 3))) * NPOINT + (size_t)i;
        }
        out[e] = v;
    }
}

extern "C" void kernel_launch(void* const* d_in, const int* in_sizes, int n_in,
                              void* d_out, int out_size) {
    const float* coords = (const float*)d_in[0];
    const float* values = (const float*)d_in[1];
    float* out = (float*)d_out;

    Cfg cfg;
    build_config(&cfg);

    const int smem_bytes = 3 * NPTS * 4 + NPOINT * 4 + 2 * NWARPS * 8 + 16;
    cudaFuncSetAttribute(fps_kernel, cudaFuncAttributeMaxDynamicSharedMemorySize,
                         smem_bytes);

    fps_kernel<<<BATCH * REP, THREADS, smem_bytes>>>(coords, values, out, cfg);
}

// round 17
// speedup vs baseline: 4.3291x; 4.3291x over previous
#include <cuda_runtime.h>
#include <cstdint>

// ============================================================================
// FarthestSubsample: B=16, Cc=3, Cv=64, N=8192, npoint=4096
//
// R17: cluster-4 FPS, ZERO in-loop barriers, hierarchical tagged mailboxes,
// fused gather (single kernel).
//   - 4 CTAs/batch (cluster 4), 256 thr (8 warps), 8 pts/thread, f32x2 math.
//   - Step: redux -> lane0 STS tagged warp key (parity slots) ->
//     warp0: poll 8 slots, bfly3, lanes0-3 relaxed DSMEM-send CTA key to all
//     4 ranks -> ALL warps: poll 4 cluster slots, bfly2 -> winner everywhere.
//   - Overwrite safety by parity double-buffer + tag induction (see R13-R16).
//   - Gather fused: each CTA writes output rows i in [rank*1024,(rank+1)*1024).
//
// Bit-exact invariants (validated R7-R16):
//   init: k2=threefry(key(42),(0,1)); farthest0[b]=((o0^o1)(k2,(0,b)))&8191
//   dist: d = fma(dz,dz, fma(dx,dx, dy*dy)); argmax first-occurrence.
// Output: [new_coords (16,3,4096)] ++ [new_values (16,64,4096)]
// ============================================================================

#define BATCH    16
#define NPTS     8192
#define NPOINT   4096
#define CLUSTER  4
#define THREADS  256
#define NWARPS   (THREADS / 32)       // 8
#define LPTS     (NPTS / CLUSTER)     // 2048
#define PPT      (LPTS / THREADS)     // 8
#define NPAIR    (PPT / 2)            // 4
#define SLICE    (NPOINT / CLUSTER)   // 1024
#define NCHAN    67

static inline uint32_t rotl32(uint32_t x, uint32_t r) { return (x << r) | (x >> (32 - r)); }

static void tf2x32_block(uint32_t k0, uint32_t k1, uint32_t x0, uint32_t x1,
                         uint32_t* o0, uint32_t* o1) {
    const uint32_t rA[4] = {13, 15, 26, 6};
    const uint32_t rB[4] = {17, 29, 16, 24};
    uint32_t ks0 = k0, ks1 = k1, ks2 = k0 ^ k1 ^ 0x1BD11BDAu;
    x0 += ks0; x1 += ks1;
    for (int i = 0; i < 4; i++) { x0 += x1; x1 = rotl32(x1, rA[i]); x1 ^= x0; }
    x0 += ks1; x1 += ks2 + 1u;
    for (int i = 0; i < 4; i++) { x0 += x1; x1 = rotl32(x1, rB[i]); x1 ^= x0; }
    x0 += ks2; x1 += ks0 + 2u;
    for (int i = 0; i < 4; i++) { x0 += x1; x1 = rotl32(x1, rA[i]); x1 ^= x0; }
    x0 += ks0; x1 += ks1 + 3u;
    for (int i = 0; i < 4; i++) { x0 += x1; x1 = rotl32(x1, rB[i]); x1 ^= x0; }
    x0 += ks1; x1 += ks2 + 4u;
    for (int i = 0; i < 4; i++) { x0 += x1; x1 = rotl32(x1, rA[i]); x1 ^= x0; }
    x0 += ks2; x1 += ks0 + 5u;
    *o0 = x0; *o1 = x1;
}

struct Cfg { int v[BATCH]; };

static void build_config(Cfg* cfg) {
    uint32_t k2a, k2b;
    tf2x32_block(0u, 42u, 0u, 1u, &k2a, &k2b);
    for (int b = 0; b < BATCH; b++) {
        uint32_t o0, o1;
        tf2x32_block(k2a, k2b, 0u, (uint32_t)b, &o0, &o1);
        cfg->v[b] = (int)((o0 ^ o1) & (NPTS - 1));
    }
}

// ---- helpers ----
__device__ __forceinline__ uint32_t smem_u32(const void* p) {
    uint32_t a;
    asm("{ .reg .u64 t; cvta.to.shared.u64 t, %1; cvt.u32.u64 %0, t; }"
        : "=r"(a) : "l"(p));
    return a;
}
__device__ __forceinline__ uint32_t mapa_u32(uint32_t addr, uint32_t rank) {
    uint32_t r;
    asm("mapa.shared::cluster.u32 %0, %1, %2;" : "=r"(r) : "r"(addr), "r"(rank));
    return r;
}
__device__ __forceinline__ void st_rlx_cluster_u64(uint32_t addr, unsigned long long v) {
    asm volatile("st.relaxed.cluster.shared::cluster.u64 [%0], %1;"
                 :: "r"(addr), "l"(v) : "memory");
}
__device__ __forceinline__ void st_vol_u64(uint32_t addr, unsigned long long v) {
    asm volatile("st.volatile.shared.u64 [%0], %1;" :: "r"(addr), "l"(v) : "memory");
}
__device__ __forceinline__ unsigned long long ld_vol_u64(uint32_t addr) {
    unsigned long long v;
    asm volatile("ld.volatile.shared.u64 %0, [%1];" : "=l"(v) : "r"(addr) : "memory");
    return v;
}
__device__ __forceinline__ unsigned long long pack2(float lo, float hi) {
    unsigned long long r;
    asm("mov.b64 %0, {%1, %2};" : "=l"(r) : "f"(lo), "f"(hi));
    return r;
}
__device__ __forceinline__ void unpack2(unsigned long long v, float& lo, float& hi) {
    asm("mov.b64 {%0, %1}, %2;" : "=f"(lo), "=f"(hi) : "l"(v));
}
__device__ __forceinline__ unsigned long long add2(unsigned long long a, unsigned long long b) {
    unsigned long long r; asm("add.rn.f32x2 %0, %1, %2;" : "=l"(r) : "l"(a), "l"(b)); return r;
}
__device__ __forceinline__ unsigned long long mul2(unsigned long long a, unsigned long long b) {
    unsigned long long r; asm("mul.rn.f32x2 %0, %1, %2;" : "=l"(r) : "l"(a), "l"(b)); return r;
}
__device__ __forceinline__ unsigned long long fma2(unsigned long long a, unsigned long long b,
                                                   unsigned long long c) {
    unsigned long long r; asm("fma.rn.f32x2 %0, %1, %2, %3;" : "=l"(r) : "l"(a), "l"(b), "l"(c)); return r;
}

#define CO (BATCH * 3 * NPOINT)

__global__ __launch_bounds__(THREADS, 1) __cluster_dims__(CLUSTER, 1, 1)
void fps_kernel(const float* __restrict__ coords,
                const float* __restrict__ values,
                float* __restrict__ out, Cfg cfg) {
    extern __shared__ float smem[];
    float* sx = smem;                             // NPTS
    float* sy = smem + NPTS;                      // NPTS
    float* sz = smem + 2 * NPTS;                  // NPTS
    int*   sidx = (int*)(smem + 3 * NPTS);        // NPOINT
    unsigned long long* swarp =
        (unsigned long long*)(smem + 3 * NPTS + NPOINT);   // 2*NWARPS (parity)
    unsigned long long* mbox = swarp + 2 * NWARPS;         // 2*CLUSTER (parity)

    const int b   = blockIdx.x / CLUSTER;
    uint32_t rank; asm("mov.u32 %0, %%cluster_ctarank;" : "=r"(rank));
    const int tid  = threadIdx.x;
    const int lane = tid & 31;
    const int warp = tid >> 5;
    const float* cb = coords + (size_t)b * 3 * NPTS;
    const float* vb = values + (size_t)b * 64 * NPTS;

    for (int i = tid; i < NPTS; i += THREADS) {
        sx[i] = cb[i]; sy[i] = cb[NPTS + i]; sz[i] = cb[2 * NPTS + i];
    }
    const int gbase = (int)rank * LPTS;
    unsigned long long p2x[NPAIR], p2y[NPAIR], p2z[NPAIR];
    float dist[PPT];
#pragma unroll
    for (int k = 0; k < NPAIR; k++) {
        int g0 = gbase + tid + (2 * k) * THREADS;
        int g1 = gbase + tid + (2 * k + 1) * THREADS;
        p2x[k] = pack2(cb[g0], cb[g1]);
        p2y[k] = pack2(cb[NPTS + g0], cb[NPTS + g1]);
        p2z[k] = pack2(cb[2 * NPTS + g0], cb[2 * NPTS + g1]);
        dist[2 * k] = 1e10f; dist[2 * k + 1] = 1e10f;
    }
    if (tid < 2 * NWARPS) swarp[tid] = 0ull;      // tag 0 never expected
    if (tid < 2 * CLUSTER) mbox[tid] = 0ull;
    __syncthreads();
    asm volatile("barrier.cluster.arrive.aligned;" ::: "memory");
    asm volatile("barrier.cluster.wait.aligned;" ::: "memory");

    const uint32_t sw_a = smem_u32(swarp);
    const uint32_t mb_a = smem_u32(mbox);
    // warp0 lane r (r<4) sends to CTA r's mbox
    const uint32_t peer_addr = (lane < CLUSTER) ? mapa_u32(mb_a, (uint32_t)lane) : 0u;

    int farthest = cfg.v[b];

    for (int t = 0; t < NPOINT; t++) {
        if (tid == 0) sidx[t] = farthest;

        const float cx = sx[farthest], cy = sy[farthest], cz = sz[farthest];
        const unsigned long long ncx = pack2(-cx, -cx);
        const unsigned long long ncy = pack2(-cy, -cy);
        const unsigned long long ncz = pack2(-cz, -cz);

        float bv = -1.0f; int bi = 0;
#pragma unroll
        for (int k = 0; k < NPAIR; k++) {
            unsigned long long dx = add2(p2x[k], ncx);
            unsigned long long dy = add2(p2y[k], ncy);
            unsigned long long dz = add2(p2z[k], ncz);
            // bit-exact V2: d = fma(dz,dz, fma(dx,dx, dy*dy)) per lane
            unsigned long long d2 = fma2(dz, dz, fma2(dx, dx, mul2(dy, dy)));
            float dlo, dhi; unpack2(d2, dlo, dhi);
            float n0 = fminf(dist[2 * k], dlo);
            float n1 = fminf(dist[2 * k + 1], dhi);
            dist[2 * k] = n0; dist[2 * k + 1] = n1;
            if (n0 > bv) { bv = n0; bi = gbase + tid + (2 * k) * THREADS; }
            if (n1 > bv) { bv = n1; bi = gbase + tid + (2 * k + 1) * THREADS; }
        }

        // warp argmax via redux (dist >= 0 -> float bits monotone)
        uint32_t fb   = __float_as_uint(bv);
        uint32_t wmax = __reduce_max_sync(0xffffffffu, fb);
        uint32_t cand = (fb == wmax) ? (uint32_t)bi : 0xffffffffu;
        uint32_t widx = __reduce_min_sync(0xffffffffu, cand);
        const uint32_t tag = (uint32_t)((t + 1) & 0x1fff);
        // key = {fbits:[26,58) | invidx:[13,26) | tag:[0,13)}
        unsigned long long key = ((unsigned long long)wmax << 26)
                               | ((unsigned long long)(NPTS - 1 - widx) << 13)
                               | (unsigned long long)tag;

        const uint32_t par8 = (uint32_t)(t & 1) * NWARPS;
        const uint32_t par4 = (uint32_t)(t & 1) * CLUSTER;

        // post warp key (parity slot)
        if (lane == 0)
            st_vol_u64(sw_a + (par8 + (uint32_t)warp) * 8, key);

        // warp0: gather 8 warp keys, reduce, send CTA key to all 4 ranks
        if (warp == 0) {
            uint32_t a = sw_a + (par8 + (uint32_t)(lane & 7)) * 8;
            unsigned long long v;
            do { v = ld_vol_u64(a); } while ((uint32_t)(v & 0x1fff) != tag);
            key = v;
#pragma unroll
            for (int off = 1; off < 8; off <<= 1) {
                unsigned long long o = __shfl_xor_sync(0xffffffffu, key, off);
                if (o > key) key = o;
            }
            if (lane < CLUSTER)
                st_rlx_cluster_u64(peer_addr + (par4 + rank) * 8, key);
        }

        // all warps: poll the 4 cluster slots, reduce -> winner in every lane
        {
            uint32_t a = mb_a + (par4 + (uint32_t)(lane & 3)) * 8;
            unsigned long long v;
            do { v = ld_vol_u64(a); } while ((uint32_t)(v & 0x1fff) != tag);
            key = v;
        }
#pragma unroll
        for (int off = 1; off < 4; off <<= 1) {
            unsigned long long o = __shfl_xor_sync(0xffffffffu, key, off);
            if (o > key) key = o;
        }
        farthest = (int)(NPTS - 1) - (int)((key >> 13) & 0x1fff);
    }

    __syncthreads();
    asm volatile("barrier.cluster.arrive.aligned;" ::: "memory");
    asm volatile("barrier.cluster.wait.aligned;" ::: "memory");

    // ---- fused gather: this CTA writes rows i in [rank*1024, rank*1024+1024) ----
    const int i0 = (int)rank * SLICE;
    for (int k = tid; k < NCHAN * SLICE; k += THREADS) {
        int c  = k >> 10;            // channel 0..66 (SLICE = 1024)
        int io = k & (SLICE - 1);
        int i  = i0 + io;
        int n  = sidx[i];
        float v;
        size_t e;
        if (c < 3) {
            v = (c == 0) ? sx[n] : (c == 1) ? sy[n] : sz[n];
            e = ((size_t)(b * 3 + c)) * NPOINT + (size_t)i;
        } else {
            v = vb[(size_t)(c - 3) * NPTS + n];
            e = (size_t)CO + ((size_t)(b * 64 + (c - 3))) * NPOINT + (size_t)i;
        }
        out[e] = v;
    }
}

extern "C" void kernel_launch(void* const* d_in, const int* in_sizes, int n_in,
                              void* d_out, int out_size) {
    const float* coords = (const float*)d_in[0];
    const float* values = (const float*)d_in[1];
    float* out = (float*)d_out;

    Cfg cfg;
    build_config(&cfg);

    const int smem_bytes = 3 * NPTS * 4 + NPOINT * 4
                         + 2 * NWARPS * 8 + 2 * CLUSTER * 8 + 16;
    cudaFuncSetAttribute(fps_kernel, cudaFuncAttributeMaxDynamicSharedMemorySize,
                         smem_bytes);

    fps_kernel<<<BATCH * CLUSTER, THREADS, smem_bytes>>>(coords, values, out, cfg);
}